// round 1
// baseline (speedup 1.0000x reference)
#include <cuda_runtime.h>

// Problem constants (fixed by setup_inputs)
#define B_  8
#define C_  24
#define H_  320
#define W_  640
#define HW_ (H_ * W_)            // 204800
#define PLANE4_ (HW_ / 4)        // 51200 float4 groups per image plane
#define NPIX4_ (B_ * PLANE4_)    // 409600 total float4 groups
#define NBHW_ (B_ * HW_)         // pred element count / prob plane base

__global__ __launch_bounds__(256)
void sparse_regression_kernel(const float* __restrict__ cost,
                              const float* __restrict__ disp,
                              float* __restrict__ out)
{
    int p = blockIdx.x * blockDim.x + threadIdx.x;
    if (p >= NPIX4_) return;

    int b = p / PLANE4_;
    int r = p - b * PLANE4_;          // float4 index within plane
    long base = (long)b * C_ * HW_ + (long)r * 4;

    // running top-2 per lane (4 lanes)
    float v0[4], v1[4];
    int   i0[4], i1[4];

    // c = 0
    {
        float4 x = *reinterpret_cast<const float4*>(cost + base);
        float xv[4] = {x.x, x.y, x.z, x.w};
        #pragma unroll
        for (int l = 0; l < 4; ++l) { v0[l] = xv[l]; i0[l] = 0; v1[l] = -3.4e38f; i1[l] = -1; }
    }
    // c = 1
    {
        float4 x = *reinterpret_cast<const float4*>(cost + base + HW_);
        float xv[4] = {x.x, x.y, x.z, x.w};
        #pragma unroll
        for (int l = 0; l < 4; ++l) {
            if (xv[l] > v0[l]) { v1[l] = v0[l]; i1[l] = i0[l]; v0[l] = xv[l]; i0[l] = 1; }
            else               { v1[l] = xv[l]; i1[l] = 1; }
        }
    }

    #pragma unroll
    for (int c = 2; c < C_; ++c) {
        float4 x = *reinterpret_cast<const float4*>(cost + base + (long)c * HW_);
        float xv[4] = {x.x, x.y, x.z, x.w};
        #pragma unroll
        for (int l = 0; l < 4; ++l) {
            float v = xv[l];
            if (v > v0[l]) {
                v1[l] = v0[l]; i1[l] = i0[l];
                v0[l] = v;     i0[l] = c;
            } else if (v > v1[l]) {
                v1[l] = v;     i1[l] = c;
            }
        }
    }

    // gather disparity at top-2 indices, 2-way softmax, weighted sum
    float pred[4], pr0[4], pr1[4];
    #pragma unroll
    for (int l = 0; l < 4; ++l) {
        long pix = (long)b * C_ * HW_ + (long)r * 4 + l;
        float d0 = __ldg(disp + pix + (long)i0[l] * HW_);
        float d1 = __ldg(disp + pix + (long)i1[l] * HW_);
        // v1 <= v0 always; e in (0,1]
        float e  = __expf(v1[l] - v0[l]);
        float inv = 1.0f / (1.0f + e);
        float p0 = inv;          // weight of the max
        float p1 = e * inv;      // weight of the second
        pr0[l] = p0;
        pr1[l] = p1;
        pred[l] = d0 * p0 + d1 * p1;
    }

    long po = (long)b * HW_ + (long)r * 4;
    *reinterpret_cast<float4*>(out + po) = make_float4(pred[0], pred[1], pred[2], pred[3]);

    // prob [B, 2, H, W] after pred
    long q0 = (long)NBHW_ + ((long)b * 2 + 0) * HW_ + (long)r * 4;
    long q1 = (long)NBHW_ + ((long)b * 2 + 1) * HW_ + (long)r * 4;
    *reinterpret_cast<float4*>(out + q0) = make_float4(pr0[0], pr0[1], pr0[2], pr0[3]);
    *reinterpret_cast<float4*>(out + q1) = make_float4(pr1[0], pr1[1], pr1[2], pr1[3]);
}

extern "C" void kernel_launch(void* const* d_in, const int* in_sizes, int n_in,
                              void* d_out, int out_size)
{
    const float* cost = (const float*)d_in[0];
    const float* disp = (const float*)d_in[1];
    float* out = (float*)d_out;

    const int threads = 256;
    const int blocks = (NPIX4_ + threads - 1) / threads;
    sparse_regression_kernel<<<blocks, threads>>>(cost, disp, out);
}